// round 4
// baseline (speedup 1.0000x reference)
#include <cuda_runtime.h>

// Shapes fixed per reference: N=100000, E=1200000, B=100000, IDIM=128, H1=H2=64.
#define NMAX 100000
#define EMAX 1200000
#define BMAX 100000

__device__ float g_deg_out[NMAX];     // rsqrt(max(out_deg,1))
__device__ float g_deg_in [NMAX];     // rsqrt(max(in_deg,1))
__device__ int   g_cnt_out[NMAX];
__device__ int   g_cnt_in [NMAX];
__device__ int   g_offs   [NMAX];     // CSR row starts (by dst)
__device__ int   g_cur    [NMAX];     // fill cursors; == row end after fill
__device__ int   g_bsum   [128];      // scan block sums
__device__ int   g_csr    [EMAX];     // src ids grouped by dst
__device__ float g_h  [NMAX * 64];    // pre-aggregation features
__device__ float g_v  [NMAX * 64];    // node features v1 / v2
__device__ float g_emb[BMAX * 64];    // fc1 output (pre-BN2)
__device__ float g_stats[256];        // [0:64) sum1 [64:128) sq1 [128:192) sum2 [192:256) sq2

__device__ __forceinline__ float lrelu(float v) { return v > 0.0f ? v : 0.01f * v; }

// ---------------------------------------------------------------------------
__global__ void k_init0(int n) {
    int i = blockIdx.x * blockDim.x + threadIdx.x;
    int st = gridDim.x * blockDim.x;
    for (int j = i; j < n; j += st) { g_cnt_out[j] = 0; g_cnt_in[j] = 0; }
    if (i < 256) g_stats[i] = 0.0f;
}

__global__ void k_deg(const int* __restrict__ src, const int* __restrict__ dst, int E) {
    int e = blockIdx.x * blockDim.x + threadIdx.x;
    if (e < E) {
        atomicAdd(&g_cnt_out[src[e]], 1);
        atomicAdd(&g_cnt_in [dst[e]], 1);
    }
}

// ---- exclusive scan of g_cnt_in -> g_offs (1024 items / block) ----
__global__ void k_scan1(int n) {
    __shared__ int sh[256];
    int t = threadIdx.x, b = blockIdx.x;
    int base = b * 1024 + t * 4;
    int v0 = (base + 0 < n) ? g_cnt_in[base + 0] : 0;
    int v1 = (base + 1 < n) ? g_cnt_in[base + 1] : 0;
    int v2 = (base + 2 < n) ? g_cnt_in[base + 2] : 0;
    int v3 = (base + 3 < n) ? g_cnt_in[base + 3] : 0;
    int tsum = v0 + v1 + v2 + v3;
    sh[t] = tsum;
    __syncthreads();
    for (int o = 1; o < 256; o <<= 1) {
        int x = (t >= o) ? sh[t - o] : 0;
        __syncthreads();
        sh[t] += x;
        __syncthreads();
    }
    int excl = sh[t] - tsum;
    if (base + 0 < n) g_offs[base + 0] = excl;
    if (base + 1 < n) g_offs[base + 1] = excl + v0;
    if (base + 2 < n) g_offs[base + 2] = excl + v0 + v1;
    if (base + 3 < n) g_offs[base + 3] = excl + v0 + v1 + v2;
    if (t == 255) g_bsum[b] = sh[255];
}

// parallel exclusive scan of up to 128 block sums (was serial single-thread)
__global__ void k_scan2(int nblk) {
    __shared__ int sh[128];
    int t = threadIdx.x;
    int v = (t < nblk) ? g_bsum[t] : 0;
    sh[t] = v;
    __syncthreads();
    #pragma unroll
    for (int o = 1; o < 128; o <<= 1) {
        int x = (t >= o) ? sh[t - o] : 0;
        __syncthreads();
        sh[t] += x;
        __syncthreads();
    }
    if (t < nblk) g_bsum[t] = sh[t] - v;
}

// add block offsets; init cursors; finalize degree scales
__global__ void k_scan3(int n) {
    int i = blockIdx.x * blockDim.x + threadIdx.x;
    if (i < n) {
        int off = g_offs[i] + g_bsum[i >> 10];
        g_offs[i] = off;
        g_cur[i]  = off;
        g_deg_in [i] = rsqrtf(fmaxf((float)g_cnt_in [i], 1.0f));
        g_deg_out[i] = rsqrtf(fmaxf((float)g_cnt_out[i], 1.0f));
    }
}

__global__ void k_fill(const int* __restrict__ src, const int* __restrict__ dst, int E) {
    int e = blockIdx.x * blockDim.x + threadIdx.x;
    if (e < E) {
        int d = dst[e];
        int p = atomicAdd(&g_cur[d], 1);
        g_csr[p] = src[e];
    }
}

// ---------------------------------------------------------------------------
// GEMM1: g_h[n,64] = (x[n,128] * rsqrt(max(cnt_out,1))) @ W1[128,64]
// Reads cnt_out directly (only needs k_deg, not scan3) so it can launch early.
// ---------------------------------------------------------------------------
__global__ __launch_bounds__(256) void k_gemm1(const float* __restrict__ x,
                                               const float* __restrict__ W, int n) {
    __shared__ float xs[128][33];
    __shared__ float ws[32][64];
    __shared__ float ds[128];
    int t = threadIdx.x;
    int row0 = blockIdx.x * 128;
    if (t < 128) {
        int gr = row0 + t;
        ds[t] = (gr < n) ? rsqrtf(fmaxf((float)g_cnt_out[gr], 1.0f)) : 0.0f;
    }
    int tr = t >> 3, tc = t & 7;
    int r0 = tr * 4, c0 = tc * 8;
    float acc[4][8];
    #pragma unroll
    for (int i = 0; i < 4; i++)
        #pragma unroll
        for (int j = 0; j < 8; j++) acc[i][j] = 0.0f;
    __syncthreads();
    for (int kc = 0; kc < 128; kc += 32) {
        #pragma unroll
        for (int ii = 0; ii < 16; ii++) {
            int i = t + ii * 256;
            int r = i >> 5, k = i & 31;
            int gr = row0 + r;
            xs[r][k] = (gr < n) ? x[gr * 128 + kc + k] * ds[r] : 0.0f;
        }
        #pragma unroll
        for (int ii = 0; ii < 8; ii++) {
            int i = t + ii * 256;
            int k = i >> 6, c = i & 63;
            ws[k][c] = W[(kc + k) * 64 + c];
        }
        __syncthreads();
        #pragma unroll
        for (int k = 0; k < 32; k++) {
            float xv[4];
            #pragma unroll
            for (int i = 0; i < 4; i++) xv[i] = xs[r0 + i][k];
            float4 wa = *(const float4*)&ws[k][c0];
            float4 wb = *(const float4*)&ws[k][c0 + 4];
            float wv[8] = {wa.x, wa.y, wa.z, wa.w, wb.x, wb.y, wb.z, wb.w};
            #pragma unroll
            for (int i = 0; i < 4; i++)
                #pragma unroll
                for (int j = 0; j < 8; j++) acc[i][j] = fmaf(xv[i], wv[j], acc[i][j]);
        }
        __syncthreads();
    }
    #pragma unroll
    for (int i = 0; i < 4; i++) {
        int gr = row0 + r0 + i;
        if (gr < n) {
            *(float4*)&g_h[gr * 64 + c0]     = make_float4(acc[i][0], acc[i][1], acc[i][2], acc[i][3]);
            *(float4*)&g_h[gr * 64 + c0 + 4] = make_float4(acc[i][4], acc[i][5], acc[i][6], acc[i][7]);
        }
    }
}

// ---------------------------------------------------------------------------
// Aggregate 1 (CSR): g_v[d] = sum_{e in d} g_h[src(e)] * deg_in_scale + b1,
// plus BN1 sum/sumsq stats. Warp per row, lane owns 2 channels, edge loop
// unrolled x4 (4 gathers in flight).
// ---------------------------------------------------------------------------
__global__ void k_agg1(const float* __restrict__ b1, int n) {
    __shared__ float ss[64], sq[64];
    int t = threadIdx.x;
    if (t < 64) { ss[t] = 0.0f; sq[t] = 0.0f; }
    __syncthreads();
    int lane = t & 31;
    int gw = (blockIdx.x * blockDim.x + t) >> 5;
    int nw = (gridDim.x * blockDim.x) >> 5;
    int c0 = lane * 2;
    float bx = b1[c0], by = b1[c0 + 1];
    float s0 = 0, q0 = 0, s1 = 0, q1 = 0;
    for (int row = gw; row < n; row += nw) {
        int e = g_offs[row], end = g_cur[row];
        float a0 = 0.0f, a1 = 0.0f;
        float u0 = 0.0f, u1 = 0.0f;
        for (; e + 4 <= end; e += 4) {
            int sA = __ldg(&g_csr[e + 0]);
            int sB = __ldg(&g_csr[e + 1]);
            int sC = __ldg(&g_csr[e + 2]);
            int sD = __ldg(&g_csr[e + 3]);
            float2 vA = *(const float2*)&g_h[sA * 64 + c0];
            float2 vB = *(const float2*)&g_h[sB * 64 + c0];
            float2 vC = *(const float2*)&g_h[sC * 64 + c0];
            float2 vD = *(const float2*)&g_h[sD * 64 + c0];
            a0 += vA.x + vC.x; a1 += vA.y + vC.y;
            u0 += vB.x + vD.x; u1 += vB.y + vD.y;
        }
        for (; e < end; e++) {
            int s = __ldg(&g_csr[e]);
            float2 v = *(const float2*)&g_h[s * 64 + c0];
            a0 += v.x; a1 += v.y;
        }
        a0 += u0; a1 += u1;
        float sc = g_deg_in[row];
        a0 = fmaf(a0, sc, bx);
        a1 = fmaf(a1, sc, by);
        *(float2*)&g_v[row * 64 + c0] = make_float2(a0, a1);
        s0 += a0; q0 += a0 * a0;
        s1 += a1; q1 += a1 * a1;
    }
    atomicAdd(&ss[c0], s0);     atomicAdd(&ss[c0 + 1], s1);
    atomicAdd(&sq[c0], q0);     atomicAdd(&sq[c0 + 1], q1);
    __syncthreads();
    if (t < 64) { atomicAdd(&g_stats[t], ss[t]); atomicAdd(&g_stats[64 + t], sq[t]); }
}

// ---------------------------------------------------------------------------
// GEMM2 fused: g_h = (leaky(bn1(g_v)) * deg_out_scale) @ W2[64,64]
// ---------------------------------------------------------------------------
__global__ __launch_bounds__(256) void k_gemm2f(const float* __restrict__ W,
        const float* __restrict__ bn1g, const float* __restrict__ bn1b,
        int n, float invn) {
    __shared__ float xs[128][33];
    __shared__ float ws[32][64];
    __shared__ float ds[128];
    __shared__ float bnS[64], bnB[64];
    int t = threadIdx.x;
    int row0 = blockIdx.x * 128;
    if (t < 128) { int gr = row0 + t; ds[t] = (gr < n) ? g_deg_out[gr] : 0.0f; }
    if (t >= 128 && t < 192) {
        int c = t - 128;
        float mu  = g_stats[c] * invn;
        float var = g_stats[64 + c] * invn - mu * mu;
        float s = rsqrtf(var + 1e-5f) * bn1g[c];
        bnS[c] = s;
        bnB[c] = bn1b[c] - mu * s;
    }
    int tr = t >> 3, tc = t & 7;
    int r0 = tr * 4, c0 = tc * 8;
    float acc[4][8];
    #pragma unroll
    for (int i = 0; i < 4; i++)
        #pragma unroll
        for (int j = 0; j < 8; j++) acc[i][j] = 0.0f;
    __syncthreads();
    for (int kc = 0; kc < 64; kc += 32) {
        #pragma unroll
        for (int ii = 0; ii < 16; ii++) {
            int i = t + ii * 256;
            int r = i >> 5, k = i & 31;
            int gr = row0 + r;
            int kk = kc + k;
            float v = 0.0f;
            if (gr < n) v = lrelu(fmaf(g_v[gr * 64 + kk], bnS[kk], bnB[kk])) * ds[r];
            xs[r][k] = v;
        }
        #pragma unroll
        for (int ii = 0; ii < 8; ii++) {
            int i = t + ii * 256;
            int k = i >> 6, c = i & 63;
            ws[k][c] = W[(kc + k) * 64 + c];
        }
        __syncthreads();
        #pragma unroll
        for (int k = 0; k < 32; k++) {
            float xv[4];
            #pragma unroll
            for (int i = 0; i < 4; i++) xv[i] = xs[r0 + i][k];
            float4 wa = *(const float4*)&ws[k][c0];
            float4 wb = *(const float4*)&ws[k][c0 + 4];
            float wv[8] = {wa.x, wa.y, wa.z, wa.w, wb.x, wb.y, wb.z, wb.w};
            #pragma unroll
            for (int i = 0; i < 4; i++)
                #pragma unroll
                for (int j = 0; j < 8; j++) acc[i][j] = fmaf(xv[i], wv[j], acc[i][j]);
        }
        __syncthreads();
    }
    #pragma unroll
    for (int i = 0; i < 4; i++) {
        int gr = row0 + r0 + i;
        if (gr < n) {
            *(float4*)&g_h[gr * 64 + c0]     = make_float4(acc[i][0], acc[i][1], acc[i][2], acc[i][3]);
            *(float4*)&g_h[gr * 64 + c0 + 4] = make_float4(acc[i][4], acc[i][5], acc[i][6], acc[i][7]);
        }
    }
}

// ---------------------------------------------------------------------------
// Aggregate 2 (CSR): g_v[d] = relu(sum g_h[src] * deg_in_scale + b2)
// ---------------------------------------------------------------------------
__global__ void k_agg2(const float* __restrict__ b2, int n) {
    int t = threadIdx.x;
    int lane = t & 31;
    int gw = (blockIdx.x * blockDim.x + t) >> 5;
    int nw = (gridDim.x * blockDim.x) >> 5;
    int c0 = lane * 2;
    float bx = b2[c0], by = b2[c0 + 1];
    for (int row = gw; row < n; row += nw) {
        int e = g_offs[row], end = g_cur[row];
        float a0 = 0.0f, a1 = 0.0f;
        float u0 = 0.0f, u1 = 0.0f;
        for (; e + 4 <= end; e += 4) {
            int sA = __ldg(&g_csr[e + 0]);
            int sB = __ldg(&g_csr[e + 1]);
            int sC = __ldg(&g_csr[e + 2]);
            int sD = __ldg(&g_csr[e + 3]);
            float2 vA = *(const float2*)&g_h[sA * 64 + c0];
            float2 vB = *(const float2*)&g_h[sB * 64 + c0];
            float2 vC = *(const float2*)&g_h[sC * 64 + c0];
            float2 vD = *(const float2*)&g_h[sD * 64 + c0];
            a0 += vA.x + vC.x; a1 += vA.y + vC.y;
            u0 += vB.x + vD.x; u1 += vB.y + vD.y;
        }
        for (; e < end; e++) {
            int s = __ldg(&g_csr[e]);
            float2 v = *(const float2*)&g_h[s * 64 + c0];
            a0 += v.x; a1 += v.y;
        }
        a0 += u0; a1 += u1;
        float sc = g_deg_in[row];
        a0 = fmaxf(fmaf(a0, sc, bx), 0.0f);
        a1 = fmaxf(fmaf(a1, sc, by), 0.0f);
        *(float2*)&g_v[row * 64 + c0] = make_float2(a0, a1);
    }
}

// ---------------------------------------------------------------------------
// fc1 fused: emb = v[i0]-v[i1]; g_emb = emb @ fc1_w + fc1_b; BN2 stats.
// ---------------------------------------------------------------------------
__global__ __launch_bounds__(256) void k_fc1(const int* __restrict__ bidx,
        const float* __restrict__ W, const float* __restrict__ bias, int Bn) {
    __shared__ float xs[128][33];
    __shared__ float ws[32][64];
    __shared__ int i0s[128], i1s[128];
    __shared__ float ss[64], sq[64];
    int t = threadIdx.x;
    int row0 = blockIdx.x * 128;
    if (t < 128) {
        int gr = row0 + t;
        i0s[t] = (gr < Bn) ? bidx[gr] : 0;
        i1s[t] = (gr < Bn) ? bidx[Bn + gr] : 0;
    }
    if (t >= 128 && t < 192) { ss[t - 128] = 0.0f; sq[t - 128] = 0.0f; }
    int tr = t >> 3, tc = t & 7;
    int r0 = tr * 4, c0 = tc * 8;
    float acc[4][8];
    #pragma unroll
    for (int i = 0; i < 4; i++)
        #pragma unroll
        for (int j = 0; j < 8; j++) acc[i][j] = 0.0f;
    __syncthreads();
    for (int kc = 0; kc < 64; kc += 32) {
        #pragma unroll
        for (int ii = 0; ii < 16; ii++) {
            int i = t + ii * 256;
            int r = i >> 5, k = i & 31;
            int kk = kc + k;
            float v = 0.0f;
            if (row0 + r < Bn) v = g_v[i0s[r] * 64 + kk] - g_v[i1s[r] * 64 + kk];
            xs[r][k] = v;
        }
        #pragma unroll
        for (int ii = 0; ii < 8; ii++) {
            int i = t + ii * 256;
            int k = i >> 6, c = i & 63;
            ws[k][c] = W[(kc + k) * 64 + c];
        }
        __syncthreads();
        #pragma unroll
        for (int k = 0; k < 32; k++) {
            float xv[4];
            #pragma unroll
            for (int i = 0; i < 4; i++) xv[i] = xs[r0 + i][k];
            float4 wa = *(const float4*)&ws[k][c0];
            float4 wb = *(const float4*)&ws[k][c0 + 4];
            float wv[8] = {wa.x, wa.y, wa.z, wa.w, wb.x, wb.y, wb.z, wb.w};
            #pragma unroll
            for (int i = 0; i < 4; i++)
                #pragma unroll
                for (int j = 0; j < 8; j++) acc[i][j] = fmaf(xv[i], wv[j], acc[i][j]);
        }
        __syncthreads();
    }
    float bj[8];
    #pragma unroll
    for (int j = 0; j < 8; j++) bj[j] = bias[c0 + j];
    float sa[8], qa[8];
    #pragma unroll
    for (int j = 0; j < 8; j++) { sa[j] = 0.0f; qa[j] = 0.0f; }
    #pragma unroll
    for (int i = 0; i < 4; i++) {
        int gr = row0 + r0 + i;
        if (gr < Bn) {
            float a[8];
            #pragma unroll
            for (int j = 0; j < 8; j++) {
                a[j] = acc[i][j] + bj[j];
                sa[j] += a[j];
                qa[j] += a[j] * a[j];
            }
            *(float4*)&g_emb[gr * 64 + c0]     = make_float4(a[0], a[1], a[2], a[3]);
            *(float4*)&g_emb[gr * 64 + c0 + 4] = make_float4(a[4], a[5], a[6], a[7]);
        }
    }
    #pragma unroll
    for (int j = 0; j < 8; j++) {
        atomicAdd(&ss[c0 + j], sa[j]);
        atomicAdd(&sq[c0 + j], qa[j]);
    }
    __syncthreads();
    if (t < 64) {
        atomicAdd(&g_stats[128 + t], ss[t]);
        atomicAdd(&g_stats[192 + t], sq[t]);
    }
}

// ---------------------------------------------------------------------------
// Final fused: y = leaky(bn2(g_emb)); z = leaky(y @ fc2_w + fc2_b);
// out = z @ fc3_w + fc3_b.
// ---------------------------------------------------------------------------
__global__ __launch_bounds__(256) void k_final(const float* __restrict__ W2,
        const float* __restrict__ b2f, const float* __restrict__ w3,
        const float* __restrict__ b3,  const float* __restrict__ g2,
        const float* __restrict__ bb2, int Bn, float invB,
        float* __restrict__ out) {
    __shared__ float xs[128][33];
    __shared__ float ws[32][64];
    __shared__ float bnS[64], bnB[64], w3s[64];
    __shared__ float red[128][8];
    int t = threadIdx.x;
    int row0 = blockIdx.x * 128;
    if (t < 64) {
        float mu  = g_stats[128 + t] * invB;
        float var = g_stats[192 + t] * invB - mu * mu;
        float s = rsqrtf(var + 1e-5f) * g2[t];
        bnS[t] = s;
        bnB[t] = bb2[t] - mu * s;
        w3s[t] = w3[t];
    }
    int tr = t >> 3, tc = t & 7;
    int r0 = tr * 4, c0 = tc * 8;
    float acc[4][8];
    #pragma unroll
    for (int i = 0; i < 4; i++)
        #pragma unroll
        for (int j = 0; j < 8; j++) acc[i][j] = 0.0f;
    __syncthreads();
    for (int kc = 0; kc < 64; kc += 32) {
        #pragma unroll
        for (int ii = 0; ii < 16; ii++) {
            int i = t + ii * 256;
            int r = i >> 5, k = i & 31;
            int gr = row0 + r;
            int kk = kc + k;
            float v = 0.0f;
            if (gr < Bn) v = lrelu(fmaf(g_emb[gr * 64 + kk], bnS[kk], bnB[kk]));
            xs[r][k] = v;
        }
        #pragma unroll
        for (int ii = 0; ii < 8; ii++) {
            int i = t + ii * 256;
            int k = i >> 6, c = i & 63;
            ws[k][c] = W2[(kc + k) * 64 + c];
        }
        __syncthreads();
        #pragma unroll
        for (int k = 0; k < 32; k++) {
            float xv[4];
            #pragma unroll
            for (int i = 0; i < 4; i++) xv[i] = xs[r0 + i][k];
            float4 wa = *(const float4*)&ws[k][c0];
            float4 wb = *(const float4*)&ws[k][c0 + 4];
            float wv[8] = {wa.x, wa.y, wa.z, wa.w, wb.x, wb.y, wb.z, wb.w};
            #pragma unroll
            for (int i = 0; i < 4; i++)
                #pragma unroll
                for (int j = 0; j < 8; j++) acc[i][j] = fmaf(xv[i], wv[j], acc[i][j]);
        }
        __syncthreads();
    }
    float bj[8], w3v[8];
    #pragma unroll
    for (int j = 0; j < 8; j++) { bj[j] = b2f[c0 + j]; w3v[j] = w3s[c0 + j]; }
    #pragma unroll
    for (int i = 0; i < 4; i++) {
        float p = 0.0f;
        #pragma unroll
        for (int j = 0; j < 8; j++) {
            float a = lrelu(acc[i][j] + bj[j]);
            p = fmaf(a, w3v[j], p);
        }
        red[r0 + i][tc] = p;
    }
    __syncthreads();
    if (t < 128) {
        int gr = row0 + t;
        if (gr < Bn) {
            float s = 0.0f;
            #pragma unroll
            for (int j = 0; j < 8; j++) s += red[t][j];
            out[gr] = s + b3[0];
        }
    }
}

// ---------------------------------------------------------------------------
extern "C" void kernel_launch(void* const* d_in, const int* in_sizes, int n_in,
                              void* d_out, int out_size) {
    const float* x    = (const float*)d_in[0];
    const int*   src  = (const int*)  d_in[1];
    const int*   dst  = (const int*)  d_in[2];
    const int*   bidx = (const int*)  d_in[3];
    const float* W1   = (const float*)d_in[4];
    const float* b1   = (const float*)d_in[5];
    const float* W2   = (const float*)d_in[6];
    const float* b2   = (const float*)d_in[7];
    const float* fc1w = (const float*)d_in[8];
    const float* fc1b = (const float*)d_in[9];
    const float* fc2w = (const float*)d_in[10];
    const float* fc2b = (const float*)d_in[11];
    const float* fc3w = (const float*)d_in[12];
    const float* fc3b = (const float*)d_in[13];
    const float* bn1g = (const float*)d_in[14];
    const float* bn1b = (const float*)d_in[15];
    const float* bn2g = (const float*)d_in[16];
    const float* bn2b = (const float*)d_in[17];

    int n  = in_sizes[0] / 128;   // nodes
    int E  = in_sizes[1];         // edges
    int Bn = in_sizes[3] / 2;     // pairs
    float* out = (float*)d_out;

    int eb  = (E + 255) / 256;
    int nb  = (n + 255) / 256;
    int nsb = (n + 1023) / 1024;
    int gb  = (n + 127) / 128;
    int gbB = (Bn + 127) / 128;

    // CSR build + degree scales; gemm1 moved to slot 4 (only needs k_deg)
    k_init0<<<512, 256>>>(n);
    k_deg  <<<eb, 256>>>(src, dst, E);
    k_scan1<<<nsb, 256>>>(n);
    k_gemm1<<<gb, 256>>>(x, W1, n);
    k_scan2<<<1, 128>>>(nsb);
    k_scan3<<<nb, 256>>>(n);
    k_fill <<<eb, 256>>>(src, dst, E);

    // conv1 aggregation
    k_agg1 <<<2048, 256>>>(b1, n);

    // conv2 (bn1 + leaky fused into gemm2 load)
    k_gemm2f<<<gb, 256>>>(W2, bn1g, bn1b, n, 1.0f / n);
    k_agg2  <<<2048, 256>>>(b2, n);

    // head
    k_fc1  <<<gbB, 256>>>(bidx, fc1w, fc1b, Bn);
    k_final<<<gbB, 256>>>(fc2w, fc2b, fc3w, fc3b, bn2g, bn2b, Bn, 1.0f / Bn, out);
}

// round 5
// speedup vs baseline: 1.0759x; 1.0759x over previous
#include <cuda_runtime.h>

// Shapes fixed per reference: N=100000, E=1200000, B=100000, IDIM=128, H1=H2=64.
#define NMAX 100000
#define EMAX 1200000
#define BMAX 100000

typedef unsigned long long ull;

__device__ float g_deg_out[NMAX];     // rsqrt(max(out_deg,1))
__device__ float g_deg_in [NMAX];     // rsqrt(max(in_deg,1))
__device__ int   g_cnt_out[NMAX];
__device__ int   g_cnt_in [NMAX];
__device__ int   g_offs   [NMAX];     // CSR row starts (by dst)
__device__ int   g_cur    [NMAX];     // fill cursors; == row end after fill
__device__ int   g_bsum   [128];      // scan block sums
__device__ int   g_csr    [EMAX];     // src ids grouped by dst
__device__ float g_h  [NMAX * 64];    // pre-aggregation features
__device__ float g_v  [NMAX * 64];    // node features v1 / v2
__device__ float g_emb[BMAX * 64];    // fc1 output (pre-BN2)
__device__ float g_stats[256];        // [0:64) sum1 [64:128) sq1 [128:192) sum2 [192:256) sq2

__device__ __forceinline__ float lrelu(float v) { return v > 0.0f ? v : 0.01f * v; }

// Packed fp32x2 helpers (Blackwell dual-FP32 pipe; FFMA2 only via PTX).
#define FMA2(d, a, b) asm("fma.rn.f32x2 %0, %1, %2, %0;" : "+l"(d) : "l"(a), "l"(b))
__device__ __forceinline__ ull bcast2(float x) {
    ull r; asm("mov.b64 %0, {%1, %1};" : "=l"(r) : "f"(x)); return r;
}
__device__ __forceinline__ void unpack2(ull p, float& lo, float& hi) {
    asm("mov.b64 {%0, %1}, %2;" : "=f"(lo), "=f"(hi) : "l"(p));
}

// ---------------------------------------------------------------------------
__global__ void k_init0(int n) {
    int i = blockIdx.x * blockDim.x + threadIdx.x;
    int st = gridDim.x * blockDim.x;
    for (int j = i; j < n; j += st) { g_cnt_out[j] = 0; g_cnt_in[j] = 0; }
    if (i < 256) g_stats[i] = 0.0f;
}

__global__ void k_deg(const int* __restrict__ src, const int* __restrict__ dst, int E) {
    int e = blockIdx.x * blockDim.x + threadIdx.x;
    if (e < E) {
        atomicAdd(&g_cnt_out[src[e]], 1);
        atomicAdd(&g_cnt_in [dst[e]], 1);
    }
}

// ---- exclusive scan of g_cnt_in -> g_offs (1024 items / block) ----
__global__ void k_scan1(int n) {
    __shared__ int sh[256];
    int t = threadIdx.x, b = blockIdx.x;
    int base = b * 1024 + t * 4;
    int v0 = (base + 0 < n) ? g_cnt_in[base + 0] : 0;
    int v1 = (base + 1 < n) ? g_cnt_in[base + 1] : 0;
    int v2 = (base + 2 < n) ? g_cnt_in[base + 2] : 0;
    int v3 = (base + 3 < n) ? g_cnt_in[base + 3] : 0;
    int tsum = v0 + v1 + v2 + v3;
    sh[t] = tsum;
    __syncthreads();
    for (int o = 1; o < 256; o <<= 1) {
        int x = (t >= o) ? sh[t - o] : 0;
        __syncthreads();
        sh[t] += x;
        __syncthreads();
    }
    int excl = sh[t] - tsum;
    if (base + 0 < n) g_offs[base + 0] = excl;
    if (base + 1 < n) g_offs[base + 1] = excl + v0;
    if (base + 2 < n) g_offs[base + 2] = excl + v0 + v1;
    if (base + 3 < n) g_offs[base + 3] = excl + v0 + v1 + v2;
    if (t == 255) g_bsum[b] = sh[255];
}

__global__ void k_scan2(int nblk) {
    __shared__ int sh[128];
    int t = threadIdx.x;
    int v = (t < nblk) ? g_bsum[t] : 0;
    sh[t] = v;
    __syncthreads();
    #pragma unroll
    for (int o = 1; o < 128; o <<= 1) {
        int x = (t >= o) ? sh[t - o] : 0;
        __syncthreads();
        sh[t] += x;
        __syncthreads();
    }
    if (t < nblk) g_bsum[t] = sh[t] - v;
}

__global__ void k_scan3(int n) {
    int i = blockIdx.x * blockDim.x + threadIdx.x;
    if (i < n) {
        int off = g_offs[i] + g_bsum[i >> 10];
        g_offs[i] = off;
        g_cur[i]  = off;
        g_deg_in [i] = rsqrtf(fmaxf((float)g_cnt_in [i], 1.0f));
        g_deg_out[i] = rsqrtf(fmaxf((float)g_cnt_out[i], 1.0f));
    }
}

__global__ void k_fill(const int* __restrict__ src, const int* __restrict__ dst, int E) {
    int e = blockIdx.x * blockDim.x + threadIdx.x;
    if (e < E) {
        int d = dst[e];
        int p = atomicAdd(&g_cur[d], 1);
        g_csr[p] = src[e];
    }
}

// ---------------------------------------------------------------------------
// GEMM1: g_h[n,64] = (x[n,128] * rsqrt(max(cnt_out,1))) @ W1[128,64]
// Packed f32x2 inner loop; 4 rows x 4 col-pairs per thread.
// ---------------------------------------------------------------------------
__global__ __launch_bounds__(256, 3) void k_gemm1(const float* __restrict__ x,
                                                  const float* __restrict__ W, int n) {
    __shared__ float xs[128][33];
    __shared__ float ws[32][64];
    __shared__ float ds[128];
    int t = threadIdx.x;
    int row0 = blockIdx.x * 128;
    if (t < 128) {
        int gr = row0 + t;
        ds[t] = (gr < n) ? rsqrtf(fmaxf((float)g_cnt_out[gr], 1.0f)) : 0.0f;
    }
    int tr = t >> 3, tc = t & 7;
    int r0 = tr * 4, c0 = tc * 8;
    ull acc[4][4];
    #pragma unroll
    for (int i = 0; i < 4; i++)
        #pragma unroll
        for (int j = 0; j < 4; j++) acc[i][j] = 0ull;
    __syncthreads();
    for (int kc = 0; kc < 128; kc += 32) {
        #pragma unroll
        for (int ii = 0; ii < 16; ii++) {
            int i = t + ii * 256;
            int r = i >> 5, k = i & 31;
            int gr = row0 + r;
            xs[r][k] = (gr < n) ? x[gr * 128 + kc + k] * ds[r] : 0.0f;
        }
        #pragma unroll
        for (int ii = 0; ii < 8; ii++) {
            int i = t + ii * 256;
            int k = i >> 6, c = i & 63;
            ws[k][c] = W[(kc + k) * 64 + c];
        }
        __syncthreads();
        #pragma unroll
        for (int k = 0; k < 32; k++) {
            ulonglong2 wA = *(const ulonglong2*)&ws[k][c0];
            ulonglong2 wB = *(const ulonglong2*)&ws[k][c0 + 4];
            #pragma unroll
            for (int i = 0; i < 4; i++) {
                ull xp = bcast2(xs[r0 + i][k]);
                FMA2(acc[i][0], xp, wA.x);
                FMA2(acc[i][1], xp, wA.y);
                FMA2(acc[i][2], xp, wB.x);
                FMA2(acc[i][3], xp, wB.y);
            }
        }
        __syncthreads();
    }
    #pragma unroll
    for (int i = 0; i < 4; i++) {
        int gr = row0 + r0 + i;
        if (gr < n) {
            float a[8];
            #pragma unroll
            for (int j = 0; j < 4; j++) unpack2(acc[i][j], a[2 * j], a[2 * j + 1]);
            *(float4*)&g_h[gr * 64 + c0]     = make_float4(a[0], a[1], a[2], a[3]);
            *(float4*)&g_h[gr * 64 + c0 + 4] = make_float4(a[4], a[5], a[6], a[7]);
        }
    }
}

// ---------------------------------------------------------------------------
// Aggregate 1 (CSR): g_v[d] = sum g_h[src]*deg_in + b1, plus BN1 stats.
// ---------------------------------------------------------------------------
__global__ void k_agg1(const float* __restrict__ b1, int n) {
    __shared__ float ss[64], sq[64];
    int t = threadIdx.x;
    if (t < 64) { ss[t] = 0.0f; sq[t] = 0.0f; }
    __syncthreads();
    int lane = t & 31;
    int gw = (blockIdx.x * blockDim.x + t) >> 5;
    int nw = (gridDim.x * blockDim.x) >> 5;
    int c0 = lane * 2;
    float bx = b1[c0], by = b1[c0 + 1];
    float s0 = 0, q0 = 0, s1 = 0, q1 = 0;
    for (int row = gw; row < n; row += nw) {
        int e = g_offs[row], end = g_cur[row];
        float a0 = 0.0f, a1 = 0.0f;
        float u0 = 0.0f, u1 = 0.0f;
        for (; e + 4 <= end; e += 4) {
            int sA = __ldg(&g_csr[e + 0]);
            int sB = __ldg(&g_csr[e + 1]);
            int sC = __ldg(&g_csr[e + 2]);
            int sD = __ldg(&g_csr[e + 3]);
            float2 vA = *(const float2*)&g_h[sA * 64 + c0];
            float2 vB = *(const float2*)&g_h[sB * 64 + c0];
            float2 vC = *(const float2*)&g_h[sC * 64 + c0];
            float2 vD = *(const float2*)&g_h[sD * 64 + c0];
            a0 += vA.x + vC.x; a1 += vA.y + vC.y;
            u0 += vB.x + vD.x; u1 += vB.y + vD.y;
        }
        for (; e < end; e++) {
            int s = __ldg(&g_csr[e]);
            float2 v = *(const float2*)&g_h[s * 64 + c0];
            a0 += v.x; a1 += v.y;
        }
        a0 += u0; a1 += u1;
        float sc = g_deg_in[row];
        a0 = fmaf(a0, sc, bx);
        a1 = fmaf(a1, sc, by);
        *(float2*)&g_v[row * 64 + c0] = make_float2(a0, a1);
        s0 += a0; q0 += a0 * a0;
        s1 += a1; q1 += a1 * a1;
    }
    atomicAdd(&ss[c0], s0);     atomicAdd(&ss[c0 + 1], s1);
    atomicAdd(&sq[c0], q0);     atomicAdd(&sq[c0 + 1], q1);
    __syncthreads();
    if (t < 64) { atomicAdd(&g_stats[t], ss[t]); atomicAdd(&g_stats[64 + t], sq[t]); }
}

// ---------------------------------------------------------------------------
// GEMM2 fused: g_h = (leaky(bn1(g_v)) * deg_out_scale) @ W2[64,64]
// ---------------------------------------------------------------------------
__global__ __launch_bounds__(256, 3) void k_gemm2f(const float* __restrict__ W,
        const float* __restrict__ bn1g, const float* __restrict__ bn1b,
        int n, float invn) {
    __shared__ float xs[128][33];
    __shared__ float ws[32][64];
    __shared__ float ds[128];
    __shared__ float bnS[64], bnB[64];
    int t = threadIdx.x;
    int row0 = blockIdx.x * 128;
    if (t < 128) { int gr = row0 + t; ds[t] = (gr < n) ? g_deg_out[gr] : 0.0f; }
    if (t >= 128 && t < 192) {
        int c = t - 128;
        float mu  = g_stats[c] * invn;
        float var = g_stats[64 + c] * invn - mu * mu;
        float s = rsqrtf(var + 1e-5f) * bn1g[c];
        bnS[c] = s;
        bnB[c] = bn1b[c] - mu * s;
    }
    int tr = t >> 3, tc = t & 7;
    int r0 = tr * 4, c0 = tc * 8;
    ull acc[4][4];
    #pragma unroll
    for (int i = 0; i < 4; i++)
        #pragma unroll
        for (int j = 0; j < 4; j++) acc[i][j] = 0ull;
    __syncthreads();
    for (int kc = 0; kc < 64; kc += 32) {
        #pragma unroll
        for (int ii = 0; ii < 16; ii++) {
            int i = t + ii * 256;
            int r = i >> 5, k = i & 31;
            int gr = row0 + r;
            int kk = kc + k;
            float v = 0.0f;
            if (gr < n) v = lrelu(fmaf(g_v[gr * 64 + kk], bnS[kk], bnB[kk])) * ds[r];
            xs[r][k] = v;
        }
        #pragma unroll
        for (int ii = 0; ii < 8; ii++) {
            int i = t + ii * 256;
            int k = i >> 6, c = i & 63;
            ws[k][c] = W[(kc + k) * 64 + c];
        }
        __syncthreads();
        #pragma unroll
        for (int k = 0; k < 32; k++) {
            ulonglong2 wA = *(const ulonglong2*)&ws[k][c0];
            ulonglong2 wB = *(const ulonglong2*)&ws[k][c0 + 4];
            #pragma unroll
            for (int i = 0; i < 4; i++) {
                ull xp = bcast2(xs[r0 + i][k]);
                FMA2(acc[i][0], xp, wA.x);
                FMA2(acc[i][1], xp, wA.y);
                FMA2(acc[i][2], xp, wB.x);
                FMA2(acc[i][3], xp, wB.y);
            }
        }
        __syncthreads();
    }
    #pragma unroll
    for (int i = 0; i < 4; i++) {
        int gr = row0 + r0 + i;
        if (gr < n) {
            float a[8];
            #pragma unroll
            for (int j = 0; j < 4; j++) unpack2(acc[i][j], a[2 * j], a[2 * j + 1]);
            *(float4*)&g_h[gr * 64 + c0]     = make_float4(a[0], a[1], a[2], a[3]);
            *(float4*)&g_h[gr * 64 + c0 + 4] = make_float4(a[4], a[5], a[6], a[7]);
        }
    }
}

// ---------------------------------------------------------------------------
// Aggregate 2 (CSR): g_v[d] = relu(sum g_h[src] * deg_in_scale + b2)
// ---------------------------------------------------------------------------
__global__ void k_agg2(const float* __restrict__ b2, int n) {
    int t = threadIdx.x;
    int lane = t & 31;
    int gw = (blockIdx.x * blockDim.x + t) >> 5;
    int nw = (gridDim.x * blockDim.x) >> 5;
    int c0 = lane * 2;
    float bx = b2[c0], by = b2[c0 + 1];
    for (int row = gw; row < n; row += nw) {
        int e = g_offs[row], end = g_cur[row];
        float a0 = 0.0f, a1 = 0.0f;
        float u0 = 0.0f, u1 = 0.0f;
        for (; e + 4 <= end; e += 4) {
            int sA = __ldg(&g_csr[e + 0]);
            int sB = __ldg(&g_csr[e + 1]);
            int sC = __ldg(&g_csr[e + 2]);
            int sD = __ldg(&g_csr[e + 3]);
            float2 vA = *(const float2*)&g_h[sA * 64 + c0];
            float2 vB = *(const float2*)&g_h[sB * 64 + c0];
            float2 vC = *(const float2*)&g_h[sC * 64 + c0];
            float2 vD = *(const float2*)&g_h[sD * 64 + c0];
            a0 += vA.x + vC.x; a1 += vA.y + vC.y;
            u0 += vB.x + vD.x; u1 += vB.y + vD.y;
        }
        for (; e < end; e++) {
            int s = __ldg(&g_csr[e]);
            float2 v = *(const float2*)&g_h[s * 64 + c0];
            a0 += v.x; a1 += v.y;
        }
        a0 += u0; a1 += u1;
        float sc = g_deg_in[row];
        a0 = fmaxf(fmaf(a0, sc, bx), 0.0f);
        a1 = fmaxf(fmaf(a1, sc, by), 0.0f);
        *(float2*)&g_v[row * 64 + c0] = make_float2(a0, a1);
    }
}

// ---------------------------------------------------------------------------
// fc1 fused: emb = v[i0]-v[i1]; g_emb = emb @ fc1_w + fc1_b; BN2 stats.
// ---------------------------------------------------------------------------
__global__ __launch_bounds__(256, 3) void k_fc1(const int* __restrict__ bidx,
        const float* __restrict__ W, const float* __restrict__ bias, int Bn) {
    __shared__ float xs[128][33];
    __shared__ float ws[32][64];
    __shared__ int i0s[128], i1s[128];
    __shared__ float ss[64], sq[64];
    int t = threadIdx.x;
    int row0 = blockIdx.x * 128;
    if (t < 128) {
        int gr = row0 + t;
        i0s[t] = (gr < Bn) ? bidx[gr] : 0;
        i1s[t] = (gr < Bn) ? bidx[Bn + gr] : 0;
    }
    if (t >= 128 && t < 192) { ss[t - 128] = 0.0f; sq[t - 128] = 0.0f; }
    int tr = t >> 3, tc = t & 7;
    int r0 = tr * 4, c0 = tc * 8;
    ull acc[4][4];
    #pragma unroll
    for (int i = 0; i < 4; i++)
        #pragma unroll
        for (int j = 0; j < 4; j++) acc[i][j] = 0ull;
    __syncthreads();
    for (int kc = 0; kc < 64; kc += 32) {
        #pragma unroll
        for (int ii = 0; ii < 16; ii++) {
            int i = t + ii * 256;
            int r = i >> 5, k = i & 31;
            int kk = kc + k;
            float v = 0.0f;
            if (row0 + r < Bn) v = g_v[i0s[r] * 64 + kk] - g_v[i1s[r] * 64 + kk];
            xs[r][k] = v;
        }
        #pragma unroll
        for (int ii = 0; ii < 8; ii++) {
            int i = t + ii * 256;
            int k = i >> 6, c = i & 63;
            ws[k][c] = W[(kc + k) * 64 + c];
        }
        __syncthreads();
        #pragma unroll
        for (int k = 0; k < 32; k++) {
            ulonglong2 wA = *(const ulonglong2*)&ws[k][c0];
            ulonglong2 wB = *(const ulonglong2*)&ws[k][c0 + 4];
            #pragma unroll
            for (int i = 0; i < 4; i++) {
                ull xp = bcast2(xs[r0 + i][k]);
                FMA2(acc[i][0], xp, wA.x);
                FMA2(acc[i][1], xp, wA.y);
                FMA2(acc[i][2], xp, wB.x);
                FMA2(acc[i][3], xp, wB.y);
            }
        }
        __syncthreads();
    }
    float bj[8];
    #pragma unroll
    for (int j = 0; j < 8; j++) bj[j] = bias[c0 + j];
    float sa[8], qa[8];
    #pragma unroll
    for (int j = 0; j < 8; j++) { sa[j] = 0.0f; qa[j] = 0.0f; }
    #pragma unroll
    for (int i = 0; i < 4; i++) {
        int gr = row0 + r0 + i;
        if (gr < Bn) {
            float a[8];
            #pragma unroll
            for (int j = 0; j < 4; j++) unpack2(acc[i][j], a[2 * j], a[2 * j + 1]);
            #pragma unroll
            for (int j = 0; j < 8; j++) {
                a[j] += bj[j];
                sa[j] += a[j];
                qa[j] += a[j] * a[j];
            }
            *(float4*)&g_emb[gr * 64 + c0]     = make_float4(a[0], a[1], a[2], a[3]);
            *(float4*)&g_emb[gr * 64 + c0 + 4] = make_float4(a[4], a[5], a[6], a[7]);
        }
    }
    #pragma unroll
    for (int j = 0; j < 8; j++) {
        atomicAdd(&ss[c0 + j], sa[j]);
        atomicAdd(&sq[c0 + j], qa[j]);
    }
    __syncthreads();
    if (t < 64) {
        atomicAdd(&g_stats[128 + t], ss[t]);
        atomicAdd(&g_stats[192 + t], sq[t]);
    }
}

// ---------------------------------------------------------------------------
// Final fused: y = leaky(bn2(g_emb)); z = leaky(y @ fc2_w + fc2_b);
// out = z @ fc3_w + fc3_b.
// ---------------------------------------------------------------------------
__global__ __launch_bounds__(256, 3) void k_final(const float* __restrict__ W2,
        const float* __restrict__ b2f, const float* __restrict__ w3,
        const float* __restrict__ b3,  const float* __restrict__ g2,
        const float* __restrict__ bb2, int Bn, float invB,
        float* __restrict__ out) {
    __shared__ float xs[128][33];
    __shared__ float ws[32][64];
    __shared__ float bnS[64], bnB[64], w3s[64];
    __shared__ float red[128][8];
    int t = threadIdx.x;
    int row0 = blockIdx.x * 128;
    if (t < 64) {
        float mu  = g_stats[128 + t] * invB;
        float var = g_stats[192 + t] * invB - mu * mu;
        float s = rsqrtf(var + 1e-5f) * g2[t];
        bnS[t] = s;
        bnB[t] = bb2[t] - mu * s;
        w3s[t] = w3[t];
    }
    int tr = t >> 3, tc = t & 7;
    int r0 = tr * 4, c0 = tc * 8;
    ull acc[4][4];
    #pragma unroll
    for (int i = 0; i < 4; i++)
        #pragma unroll
        for (int j = 0; j < 4; j++) acc[i][j] = 0ull;
    __syncthreads();
    for (int kc = 0; kc < 64; kc += 32) {
        #pragma unroll
        for (int ii = 0; ii < 16; ii++) {
            int i = t + ii * 256;
            int r = i >> 5, k = i & 31;
            int gr = row0 + r;
            int kk = kc + k;
            float v = 0.0f;
            if (gr < Bn) v = lrelu(fmaf(g_emb[gr * 64 + kk], bnS[kk], bnB[kk]));
            xs[r][k] = v;
        }
        #pragma unroll
        for (int ii = 0; ii < 8; ii++) {
            int i = t + ii * 256;
            int k = i >> 6, c = i & 63;
            ws[k][c] = W2[(kc + k) * 64 + c];
        }
        __syncthreads();
        #pragma unroll
        for (int k = 0; k < 32; k++) {
            ulonglong2 wA = *(const ulonglong2*)&ws[k][c0];
            ulonglong2 wB = *(const ulonglong2*)&ws[k][c0 + 4];
            #pragma unroll
            for (int i = 0; i < 4; i++) {
                ull xp = bcast2(xs[r0 + i][k]);
                FMA2(acc[i][0], xp, wA.x);
                FMA2(acc[i][1], xp, wA.y);
                FMA2(acc[i][2], xp, wB.x);
                FMA2(acc[i][3], xp, wB.y);
            }
        }
        __syncthreads();
    }
    float bj[8], w3v[8];
    #pragma unroll
    for (int j = 0; j < 8; j++) { bj[j] = b2f[c0 + j]; w3v[j] = w3s[c0 + j]; }
    #pragma unroll
    for (int i = 0; i < 4; i++) {
        float a[8];
        #pragma unroll
        for (int j = 0; j < 4; j++) unpack2(acc[i][j], a[2 * j], a[2 * j + 1]);
        float p = 0.0f;
        #pragma unroll
        for (int j = 0; j < 8; j++) {
            float v = lrelu(a[j] + bj[j]);
            p = fmaf(v, w3v[j], p);
        }
        red[r0 + i][tc] = p;
    }
    __syncthreads();
    if (t < 128) {
        int gr = row0 + t;
        if (gr < Bn) {
            float s = 0.0f;
            #pragma unroll
            for (int j = 0; j < 8; j++) s += red[t][j];
            out[gr] = s + b3[0];
        }
    }
}

// ---------------------------------------------------------------------------
extern "C" void kernel_launch(void* const* d_in, const int* in_sizes, int n_in,
                              void* d_out, int out_size) {
    const float* x    = (const float*)d_in[0];
    const int*   src  = (const int*)  d_in[1];
    const int*   dst  = (const int*)  d_in[2];
    const int*   bidx = (const int*)  d_in[3];
    const float* W1   = (const float*)d_in[4];
    const float* b1   = (const float*)d_in[5];
    const float* W2   = (const float*)d_in[6];
    const float* b2   = (const float*)d_in[7];
    const float* fc1w = (const float*)d_in[8];
    const float* fc1b = (const float*)d_in[9];
    const float* fc2w = (const float*)d_in[10];
    const float* fc2b = (const float*)d_in[11];
    const float* fc3w = (const float*)d_in[12];
    const float* fc3b = (const float*)d_in[13];
    const float* bn1g = (const float*)d_in[14];
    const float* bn1b = (const float*)d_in[15];
    const float* bn2g = (const float*)d_in[16];
    const float* bn2b = (const float*)d_in[17];

    int n  = in_sizes[0] / 128;   // nodes
    int E  = in_sizes[1];         // edges
    int Bn = in_sizes[3] / 2;     // pairs
    float* out = (float*)d_out;

    int eb  = (E + 255) / 256;
    int nb  = (n + 255) / 256;
    int nsb = (n + 1023) / 1024;
    int gb  = (n + 127) / 128;
    int gbB = (Bn + 127) / 128;

    // CSR build + degree scales; gemm1 at slot 4 (only needs k_deg)
    k_init0<<<512, 256>>>(n);
    k_deg  <<<eb, 256>>>(src, dst, E);
    k_scan1<<<nsb, 256>>>(n);
    k_gemm1<<<gb, 256>>>(x, W1, n);
    k_scan2<<<1, 128>>>(nsb);
    k_scan3<<<nb, 256>>>(n);
    k_fill <<<eb, 256>>>(src, dst, E);

    // conv1 aggregation
    k_agg1 <<<2048, 256>>>(b1, n);

    // conv2 (bn1 + leaky fused into gemm2 load)
    k_gemm2f<<<gb, 256>>>(W2, bn1g, bn1b, n, 1.0f / n);
    k_agg2  <<<2048, 256>>>(b2, n);

    // head
    k_fc1  <<<gbB, 256>>>(bidx, fc1w, fc1b, Bn);
    k_final<<<gbB, 256>>>(fc2w, fc2b, fc3w, fc3b, bn2g, bn2b, Bn, 1.0f / Bn, out);
}